// round 4
// baseline (speedup 1.0000x reference)
#include <cuda_runtime.h>

// Problem constants
#define B_  256
#define S_  2048
#define I_  128
#define J_  40    // LSTM_IN
#define G_  80    // 4*H
#define H_  20

typedef unsigned long long u64;

#define L2E 1.4426950408889634f   // log2(e)

// Scratch gx layout per (b,s): 80 floats, PRE-SCALED by log2e (gate g rows by 2*log2e):
//   float 2j   = gate i, row j      float 2j+1  = gate f, row j
//   float 40+2j = gate g, row j     float 41+2j = gate o, row j
__device__ __align__(256) float g_gx[(size_t)S_ * B_ * G_];

// ---------------- helpers ----------------
__device__ __forceinline__ u64 pk2(float lo, float hi) {
    u64 r;
    asm("mov.b64 %0, {%1, %2};" : "=l"(r) : "f"(lo), "f"(hi));
    return r;
}
__device__ __forceinline__ void upk2(u64 v, float& lo, float& hi) {
    asm("mov.b64 {%0, %1}, %2;" : "=f"(lo), "=f"(hi) : "l"(v));
}
__device__ __forceinline__ void fma2(u64& d, u64 a, u64 b) {
    asm("fma.rn.f32x2 %0, %1, %2, %0;" : "+l"(d) : "l"(a), "l"(b));
}
__device__ __forceinline__ float ex2f(float x) {
    float r;
    asm("ex2.approx.f32 %0, %1;" : "=f"(r) : "f"(x));
    return r;
}
__device__ __forceinline__ float rcpf(float x) {
    float r;
    asm("rcp.approx.f32 %0, %1;" : "=f"(r) : "f"(x));
    return r;
}

// ---------------- GEMM kernel ----------------
// gx = relu(feed@W1^T + b1) @ Wih^T + (bih+bhh), scaled by log2e (2*log2e for gate g),
// written pair-permuted, batch-major. 64-row tiles, 128 threads, 2 blocks/SM.

#define TILE_R 64

struct SmemG {
    float feed[TILE_R][I_ + 4];  // stride 132 words
    float x[TILE_R][J_ + 4];     // stride 44
    float w1[J_][I_ + 4];        // stride 132
    float wih[G_][J_ + 2];       // stride 42
    float b1v[J_];
    float b2v[G_];
};

__global__ __launch_bounds__(128, 2) void gemm_kernel(
    const float* __restrict__ feed, const float* __restrict__ W1,
    const float* __restrict__ b1, const float* __restrict__ Wih,
    const float* __restrict__ bih, const float* __restrict__ bhh)
{
    extern __shared__ char smem_raw[];
    SmemG& sm = *reinterpret_cast<SmemG*>(smem_raw);
    const int tid  = threadIdx.x;
    const int tile = blockIdx.x;           // 8192 tiles
    const int s    = tile >> 2;            // 4 tiles per timestep
    const int bb   = (tile & 3) * 64;      // batch base

    // --- stage weights/biases (gate scale folded into wih & b2v) ---
    for (int idx = tid; idx < J_ * I_; idx += 128)
        sm.w1[idx / I_][idx % I_] = W1[idx];
    for (int idx = tid; idx < G_ * J_; idx += 128) {
        int row = idx / J_;
        float sc = (row >= 40 && row < 60) ? (2.f * L2E) : L2E;
        sm.wih[row][idx % J_] = Wih[idx] * sc;
    }
    if (tid < J_) sm.b1v[tid] = b1[tid];
    if (tid < G_) {
        float sc = (tid >= 40 && tid < 60) ? (2.f * L2E) : L2E;
        sm.b2v[tid] = (bih[tid] + bhh[tid]) * sc;
    }

    // --- stage feed tile (float4, coalesced) ---
    for (int idx = tid; idx < TILE_R * (I_ / 4); idx += 128) {
        int r  = idx >> 5;
        int c4 = idx & 31;
        float4 v = *reinterpret_cast<const float4*>(
            feed + ((size_t)(bb + r) * S_ + s) * I_ + c4 * 4);
        *reinterpret_cast<float4*>(&sm.feed[r][c4 * 4]) = v;
    }
    __syncthreads();

    const int cg = tid & 7;   // 8 col groups
    const int rg = tid >> 3;  // 16 row groups; rows rg + 16q

    // --- phase 1: x[r][j], j0 = cg*5 ---
    {
        const int j0 = cg * 5;
        u64 acc[4][5];
#pragma unroll
        for (int q = 0; q < 4; q++)
#pragma unroll
            for (int p = 0; p < 5; p++) acc[q][p] = 0ull;

#pragma unroll 2
        for (int k4 = 0; k4 < I_ / 4; k4++) {
            const int k = k4 * 4;
            ulonglong2 fr[4], wj[5];
#pragma unroll
            for (int q = 0; q < 4; q++)
                fr[q] = *reinterpret_cast<const ulonglong2*>(&sm.feed[rg + 16 * q][k]);
#pragma unroll
            for (int p = 0; p < 5; p++)
                wj[p] = *reinterpret_cast<const ulonglong2*>(&sm.w1[j0 + p][k]);
#pragma unroll
            for (int q = 0; q < 4; q++)
#pragma unroll
                for (int p = 0; p < 5; p++) {
                    fma2(acc[q][p], fr[q].x, wj[p].x);
                    fma2(acc[q][p], fr[q].y, wj[p].y);
                }
        }
#pragma unroll
        for (int q = 0; q < 4; q++)
#pragma unroll
            for (int p = 0; p < 5; p++) {
                float lo, hi;
                upk2(acc[q][p], lo, hi);
                float v = lo + hi + sm.b1v[j0 + p];
                sm.x[rg + 16 * q][j0 + p] = fmaxf(v, 0.f);
            }
    }
    __syncthreads();

    // --- phase 2: cg<4 -> (i,f) pairs for j in [5cg,5cg+5); cg>=4 -> (g,o) pairs ---
    {
        const int half = cg >> 2;             // 0: rows 0/20,  1: rows 40/60
        const int j0   = 5 * (cg & 3);
        const int rb   = half * 40;           // base row of first gate in pair

        u64 acc0[4][5], acc1[4][5];
#pragma unroll
        for (int q = 0; q < 4; q++)
#pragma unroll
            for (int p = 0; p < 5; p++) { acc0[q][p] = 0ull; acc1[q][p] = 0ull; }

#pragma unroll 2
        for (int kp = 0; kp < J_ / 2; kp++) {
            const int k = kp * 2;
            u64 fr[4], w0[5], w1r[5];
#pragma unroll
            for (int q = 0; q < 4; q++)
                fr[q] = *reinterpret_cast<const u64*>(&sm.x[rg + 16 * q][k]);
#pragma unroll
            for (int p = 0; p < 5; p++) {
                w0[p]  = *reinterpret_cast<const u64*>(&sm.wih[rb + j0 + p][k]);
                w1r[p] = *reinterpret_cast<const u64*>(&sm.wih[rb + 20 + j0 + p][k]);
            }
#pragma unroll
            for (int q = 0; q < 4; q++)
#pragma unroll
                for (int p = 0; p < 5; p++) {
                    fma2(acc0[q][p], fr[q], w0[p]);
                    fma2(acc1[q][p], fr[q], w1r[p]);
                }
        }

#pragma unroll
        for (int q = 0; q < 4; q++) {
            const int r = rg + 16 * q;
            float* op = g_gx + ((size_t)(bb + r) * S_ + s) * G_ + half * 40;
#pragma unroll
            for (int p = 0; p < 5; p++) {
                float l0, h0v, l1, h1v;
                upk2(acc0[q][p], l0, h0v);
                upk2(acc1[q][p], l1, h1v);
                float v0 = l0 + h0v + sm.b2v[rb + j0 + p];
                float v1 = l1 + h1v + sm.b2v[rb + 20 + j0 + p];
                *reinterpret_cast<u64*>(op + 2 * (j0 + p)) = pk2(v0, v1);
            }
        }
    }
}

// ---------------- LSTM recurrence: one warp = 4 batch elements ----------------
// Lane j<20 owns h[j],c[j] for 4 batches. Weights k-pair packed, pre-scaled by
// log2e (g rows 2*log2e) so every activation is a bare ex2.approx.
// h broadcast through smem: 1 STS + 5 LDS.128 per batch-step.
// Shared rcp: (sig i, sig f) and (tanh g, sig o) each use one rcp.

__global__ __launch_bounds__(32, 1) void lstm_kernel(
    const float* __restrict__ Whh, const float* __restrict__ Wf,
    const float* __restrict__ bf, const float* __restrict__ h0,
    const float* __restrict__ c0, float* __restrict__ out)
{
    __shared__ __align__(16) float hsh[4][32];

    const int lane = threadIdx.x;
    const int j    = (lane < H_) ? lane : 0;
    const int qb   = blockIdx.x * 4;   // batches qb..qb+3

    // weights, k-pair packed + prescaled
    u64 wi[10], wf_[10], wg[10], wo[10];
#pragma unroll
    for (int m = 0; m < 10; m++) {
        wi[m]  = pk2(Whh[(0 * H_ + j) * H_ + 2 * m] * L2E,
                     Whh[(0 * H_ + j) * H_ + 2 * m + 1] * L2E);
        wf_[m] = pk2(Whh[(1 * H_ + j) * H_ + 2 * m] * L2E,
                     Whh[(1 * H_ + j) * H_ + 2 * m + 1] * L2E);
        wg[m]  = pk2(Whh[(2 * H_ + j) * H_ + 2 * m] * (2.f * L2E),
                     Whh[(2 * H_ + j) * H_ + 2 * m + 1] * (2.f * L2E));
        wo[m]  = pk2(Whh[(3 * H_ + j) * H_ + 2 * m] * L2E,
                     Whh[(3 * H_ + j) * H_ + 2 * m + 1] * L2E);
    }

    float h[4], c[4], hs[4];
    const float* gp[4];
#pragma unroll
    for (int b = 0; b < 4; b++) {
        h[b]  = h0[(qb + b) * H_ + j];
        c[b]  = c0[(qb + b) * H_ + j];
        hs[b] = 0.f;
        gp[b] = g_gx + (size_t)(qb + b) * S_ * G_;
    }
    const int oIF = 2 * j;
    const int oGO = 40 + 2 * j;

    // prefetch ring: slot u holds step s+u
    u64 bif[4][2], bgo[4][2];
#pragma unroll
    for (int b = 0; b < 4; b++)
#pragma unroll
        for (int u = 0; u < 2; u++) {
            bif[b][u] = *reinterpret_cast<const u64*>(gp[b] + u * G_ + oIF);
            bgo[b][u] = *reinterpret_cast<const u64*>(gp[b] + u * G_ + oGO);
        }

    for (int s = 0; s < S_; s += 2) {
#pragma unroll
        for (int u = 0; u < 2; u++) {
            // publish current h's
#pragma unroll
            for (int b = 0; b < 4; b++) hsh[b][lane] = h[b];
            __syncwarp();

            const bool pf = (s + 2 + u) < S_;
#pragma unroll
            for (int b = 0; b < 4; b++) {
                // broadcast h as k-pairs (conflict-free smem broadcast)
                u64 hp[10];
#pragma unroll
                for (int m4 = 0; m4 < 5; m4++) {
                    ulonglong2 t = *reinterpret_cast<const ulonglong2*>(&hsh[b][4 * m4]);
                    hp[2 * m4]     = t.x;
                    hp[2 * m4 + 1] = t.y;
                }
                u64 ai = 0ull, af = 0ull, ag = 0ull, ao = 0ull;
#pragma unroll
                for (int m = 0; m < 10; m++) {
                    fma2(ai, wi[m],  hp[m]);
                    fma2(af, wf_[m], hp[m]);
                    fma2(ag, wg[m],  hp[m]);
                    fma2(ao, wo[m],  hp[m]);
                }
                float gi, gf, gg, go;
                upk2(bif[b][u], gi, gf);
                upk2(bgo[b][u], gg, go);
                // prefetch step s+2+u into this slot
                if (pf) {
                    bif[b][u] = *reinterpret_cast<const u64*>(gp[b] + (2 + u) * G_ + oIF);
                    bgo[b][u] = *reinterpret_cast<const u64*>(gp[b] + (2 + u) * G_ + oGO);
                }
                float e0, e1;
                upk2(ai, e0, e1); float vi = e0 + e1 + gi;
                upk2(af, e0, e1); float vf = e0 + e1 + gf;
                upk2(ag, e0, e1); float vg = e0 + e1 + gg;
                upk2(ao, e0, e1); float vo = e0 + e1 + go;
                // activations (args already in log2 domain)
                float Ei = ex2f(vi), Ef = ex2f(vf), Eg = ex2f(vg), Eo = ex2f(vo);
                float t1 = 1.f + Ei, t2 = 1.f + Ef;
                float R1 = rcpf(t1 * t2);
                float si = Ei * t2 * R1;
                float sf = Ef * t1 * R1;
                float t3 = Eg + 1.f, t4 = Eo + 1.f, t5 = Eg - 1.f;
                float R2 = rcpf(t3 * t4);
                float tg = t5 * t4 * R2;
                float so = Eo * t3 * R2;
                c[b] = fmaf(sf, c[b], si * tg);
                float Ec = ex2f(c[b] * (2.f * L2E));
                float tc = fmaf(-2.f, rcpf(Ec + 1.f), 1.f);
                h[b] = so * tc;
                hs[b] += h[b];
            }
            __syncwarp();
        }
#pragma unroll
        for (int b = 0; b < 4; b++) gp[b] += 2 * G_;
    }

    // y = Wf @ (hsum / S) + bf (mean commutes with the linear layer)
    float wa = (lane < H_) ? Wf[lane] : 0.f;
    float wb = (lane < H_) ? Wf[H_ + lane] : 0.f;
#pragma unroll
    for (int b = 0; b < 4; b++) {
        float y0 = wa * hs[b];
        float y1 = wb * hs[b];
#pragma unroll
        for (int off = 16; off; off >>= 1) {
            y0 += __shfl_xor_sync(0xffffffffu, y0, off);
            y1 += __shfl_xor_sync(0xffffffffu, y1, off);
        }
        if (lane == 0) {
            out[2 * (qb + b) + 0] = y0 * (1.f / S_) + bf[0];
            out[2 * (qb + b) + 1] = y1 * (1.f / S_) + bf[1];
        }
    }
}

// ---------------- launch ----------------
extern "C" void kernel_launch(void* const* d_in, const int* in_sizes, int n_in,
                              void* d_out, int out_size)
{
    const float* feed = (const float*)d_in[0];
    const float* W1   = (const float*)d_in[1];
    const float* b1   = (const float*)d_in[2];
    const float* Wih  = (const float*)d_in[3];
    const float* Whh  = (const float*)d_in[4];
    const float* bih  = (const float*)d_in[5];
    const float* bhh  = (const float*)d_in[6];
    const float* Wf   = (const float*)d_in[7];
    const float* bf   = (const float*)d_in[8];
    const float* h0   = (const float*)d_in[9];
    const float* c0   = (const float*)d_in[10];
    float* out = (float*)d_out;

    cudaFuncSetAttribute(gemm_kernel, cudaFuncAttributeMaxDynamicSharedMemorySize,
                         (int)sizeof(SmemG));
    gemm_kernel<<<(S_ * B_) / TILE_R, 128, sizeof(SmemG)>>>(feed, W1, b1, Wih, bih, bhh);
    lstm_kernel<<<B_ / 4, 32>>>(Whh, Wf, bf, h0, c0, out);
}